// round 10
// baseline (speedup 1.0000x reference)
#include <cuda_runtime.h>
#include <cstdint>

#define D_MODEL 4096
#define E3      12288
#define NHEADS  32
#define HDIM    128
#define BATCH   2
#define SEQ     2048
#define ROWS    (BATCH*SEQ)   /* 4096 */
#define CLIP_V  8.0f
#define LN_EPS  1e-5f

// Scratch (allocation-free rule: __device__ globals)
__device__ float    g_qkv[(size_t)ROWS * E3];        // post-GEMM1 (q|k|v)
__device__ float    g_attn[(size_t)ROWS * D_MODEL];  // attention out (tf32-rounded)
__device__ uint32_t g_hid_tf[(size_t)ROWS * D_MODEL];     // hidden, tf32 bits
__device__ uint32_t g_wqkv_tf[(size_t)E3 * D_MODEL];      // w_qkv, tf32 bits
__device__ uint32_t g_wout_tf[(size_t)D_MODEL * D_MODEL]; // w_out, tf32 bits

// ===========================================================================
// helpers
// ===========================================================================
__device__ __forceinline__ uint32_t f2tf(float f) {
    uint32_t r;
    asm("cvt.rna.tf32.f32 %0, %1;" : "=r"(r) : "f"(f));
    return r;
}

__device__ __forceinline__ void mma_tf32(float* d, const uint32_t* a, const uint32_t* b) {
    asm volatile(
        "mma.sync.aligned.m16n8k8.row.col.f32.tf32.tf32.f32 "
        "{%0,%1,%2,%3}, {%4,%5,%6,%7}, {%8,%9}, {%0,%1,%2,%3};"
        : "+f"(d[0]), "+f"(d[1]), "+f"(d[2]), "+f"(d[3])
        : "r"(a[0]), "r"(a[1]), "r"(a[2]), "r"(a[3]), "r"(b[0]), "r"(b[1]));
}

__device__ __forceinline__ void cp16(uint32_t saddr, const void* g) {
    asm volatile("cp.async.cg.shared.global [%0], [%1], 16;"
                 :: "r"(saddr), "l"(g) : "memory");
}
#define CP_COMMIT()  asm volatile("cp.async.commit_group;" ::: "memory")
#define CP_WAIT1()   asm volatile("cp.async.wait_group 1;" ::: "memory")

__device__ __forceinline__ void ldsm4(uint32_t& r0, uint32_t& r1, uint32_t& r2,
                                      uint32_t& r3, uint32_t saddr) {
    asm volatile("ldmatrix.sync.aligned.m8n8.x4.shared.b16 {%0,%1,%2,%3}, [%4];"
                 : "=r"(r0), "=r"(r1), "=r"(r2), "=r"(r3) : "r"(saddr));
}

// ===========================================================================
// Elementwise RNA tf32 pre-conversion (bit-hoisted out of the GEMM hot loop)
// ===========================================================================
__global__ __launch_bounds__(256)
void cvt_tf32(const float4* __restrict__ in, uint4* __restrict__ out, int n4) {
    for (int i = blockIdx.x * 256 + threadIdx.x; i < n4; i += gridDim.x * 256) {
        float4 v = in[i];
        uint4 o;
        o.x = f2tf(v.x); o.y = f2tf(v.y); o.z = f2tf(v.z); o.w = f2tf(v.w);
        out[i] = o;
    }
}

// ===========================================================================
// TF32 GEMM v5: C[m][n] = sum_k A[m][k]*W[n][k]; inputs are tf32 bits.
// CTA tile 128x256, BK=32, 8 warps (2m x 4n), warp tile 64x64.
// cp.async 3-stage pipeline + ldmatrix.x4 fragment loads, zero cvt in loop.
// grid = (Ntot/256, M/128), 256 threads.
// ===========================================================================
#define LDP2  36
#define A_TW  (128*LDP2)
#define B_TW  (256*LDP2)
#define STG_W (A_TW + B_TW)
#define GEMM_SMEM (STG_W * 3 * 4)   /* 165888 B */

template<bool DO_CLIP>
__global__ __launch_bounds__(256)
void gemm_mma(const uint32_t* __restrict__ A, const uint32_t* __restrict__ W,
              float* __restrict__ C, int Ntot, int K) {
    extern __shared__ uint32_t sm[];

    const int tid  = threadIdx.x;
    const int lane = tid & 31;
    const int warp = tid >> 5;
    const int wm0  = (warp >> 2) << 6;   // 0 or 64
    const int wn0  = (warp & 3) << 6;    // 0,64,128,192
    const int m0 = blockIdx.y << 7, n0 = blockIdx.x << 8;

    const uint32_t* Ab = A + (size_t)m0 * K;
    const uint32_t* Wb = W + (size_t)n0 * K;

    const int arow = tid >> 3;
    const int ac4  = tid & 7;

    const uint32_t sbase = (uint32_t)__cvta_generic_to_shared(sm);
    const uint32_t soffA = ((uint32_t)(arow * LDP2 + ac4 * 4)) * 4;
    const uint32_t sstrA = (uint32_t)(32 * LDP2) * 4;

    // ldmatrix per-lane byte offsets (within a stage)
    const uint32_t l15   = lane & 15;
    const uint32_t csel  = ((lane >> 4) & 1) * 16;   // +4 f32 cols for lanes 16-31
    const uint32_t aOff  = ((wm0 + l15) * LDP2) * 4 + csel;
    const uint32_t bOff  = (uint32_t)(A_TW * 4) + ((wn0 + l15) * LDP2) * 4 + csel;
    const uint32_t mStr  = (uint32_t)(16 * LDP2) * 4;  // 16-row step

    float acc[4][8][4];
#pragma unroll
    for (int a = 0; a < 4; a++)
#pragma unroll
        for (int b = 0; b < 8; b++)
#pragma unroll
            for (int c = 0; c < 4; c++) acc[a][b][c] = 0.f;

    const int NS = K >> 5;

#define ISSUE_STAGE(buf, k0)                                                      \
    do {                                                                          \
        uint32_t _sa = sbase + (uint32_t)(buf) * (STG_W * 4) + soffA;             \
        uint32_t _sb = _sa + (uint32_t)(A_TW * 4);                                \
        _Pragma("unroll")                                                         \
        for (int _i = 0; _i < 4; _i++)                                            \
            cp16(_sa + _i * sstrA,                                                \
                 Ab + (size_t)(arow + 32*_i) * K + (k0) + ac4*4);                 \
        _Pragma("unroll")                                                         \
        for (int _i = 0; _i < 8; _i++)                                            \
            cp16(_sb + _i * sstrA,                                                \
                 Wb + (size_t)(arow + 32*_i) * K + (k0) + ac4*4);                 \
        CP_COMMIT();                                                              \
    } while (0)

    ISSUE_STAGE(0, 0);
    ISSUE_STAGE(1, 32);

    int cur = 0, nxt = 2;
    for (int s = 0; s < NS; s++) {
        CP_WAIT1();
        __syncthreads();
        if (s + 2 < NS) ISSUE_STAGE(nxt, (s + 2) << 5);

        const uint32_t stageB = sbase + (uint32_t)cur * (STG_W * 4);
#pragma unroll
        for (int kk = 0; kk < 4; kk++) {
            const uint32_t kbB = kk * 32;   // 8 words
            uint32_t af[4][4], bf[8][2];
#pragma unroll
            for (int mt = 0; mt < 4; mt++)
                ldsm4(af[mt][0], af[mt][1], af[mt][2], af[mt][3],
                      stageB + aOff + mt * mStr + kbB);
#pragma unroll
            for (int ntp = 0; ntp < 4; ntp++)
                ldsm4(bf[2*ntp][0], bf[2*ntp+1][0], bf[2*ntp][1], bf[2*ntp+1][1],
                      stageB + bOff + ntp * mStr + kbB);
#pragma unroll
            for (int mt = 0; mt < 4; mt++)
#pragma unroll
                for (int nt = 0; nt < 8; nt++)
                    mma_tf32(acc[mt][nt], af[mt], bf[nt]);
        }

        cur = (cur == 2) ? 0 : cur + 1;
        nxt = (nxt == 2) ? 0 : nxt + 1;
    }
#undef ISSUE_STAGE

    // epilogue
#pragma unroll
    for (int mt = 0; mt < 4; mt++) {
#pragma unroll
        for (int nt = 0; nt < 8; nt++) {
            int row = m0 + wm0 + (mt << 4) + (lane >> 2);
            int col = n0 + wn0 + (nt << 3) + ((lane & 3) << 1);
            float2 v0 = make_float2(acc[mt][nt][0], acc[mt][nt][1]);
            float2 v1 = make_float2(acc[mt][nt][2], acc[mt][nt][3]);
            if (DO_CLIP) {
                v0.x = fminf(fmaxf(v0.x, -CLIP_V), CLIP_V);
                v0.y = fminf(fmaxf(v0.y, -CLIP_V), CLIP_V);
                v1.x = fminf(fmaxf(v1.x, -CLIP_V), CLIP_V);
                v1.y = fminf(fmaxf(v1.y, -CLIP_V), CLIP_V);
            }
            *(float2*)(C + (size_t)row * Ntot + col) = v0;
            *(float2*)(C + (size_t)(row + 8) * Ntot + col) = v1;
        }
    }
}

// ---------------------------------------------------------------------------
// Fused q/k LayerNorm (unchanged)
// ---------------------------------------------------------------------------
__global__ __launch_bounds__(256)
void ln_kernel(float* __restrict__ base,
               const float* __restrict__ wq, const float* __restrict__ bq,
               const float* __restrict__ wk, const float* __restrict__ bk) {
    __shared__ float red0[8], red1[8];
    __shared__ float mu_s, inv_s;
    const float* w = blockIdx.y ? wk : wq;
    const float* b = blockIdx.y ? bk : bq;
    float* x = base + (size_t)blockIdx.x * E3 + blockIdx.y * D_MODEL;
    const int tid = threadIdx.x;

    float s = 0.f, s2 = 0.f;
    for (int i = tid; i < D_MODEL; i += 256) {
        float v = x[i]; s += v; s2 += v * v;
    }
#pragma unroll
    for (int o = 16; o; o >>= 1) {
        s  += __shfl_down_sync(0xffffffffu, s,  o);
        s2 += __shfl_down_sync(0xffffffffu, s2, o);
    }
    if ((tid & 31) == 0) { red0[tid >> 5] = s; red1[tid >> 5] = s2; }
    __syncthreads();
    if (tid == 0) {
        float S = 0.f, S2 = 0.f;
#pragma unroll
        for (int i = 0; i < 8; i++) { S += red0[i]; S2 += red1[i]; }
        float mu = S * (1.f / D_MODEL);
        float var = S2 * (1.f / D_MODEL) - mu * mu;
        mu_s = mu;
        inv_s = rsqrtf(var + LN_EPS);
    }
    __syncthreads();
    const float mu = mu_s, inv = inv_s;
    for (int i = tid; i < D_MODEL; i += 256) {
        x[i] = (x[i] - mu) * inv * w[i] + b[i];
    }
}

// ---------------------------------------------------------------------------
// Flash attention v5 (R8 core; epilogue now writes tf32-rounded output so
// GEMM2 consumes it directly — same values GEMM2's cvt produced before).
// ---------------------------------------------------------------------------
#define QSTR 128
#define KSTR 132
#define PSTR 64

__global__ __launch_bounds__(256, 2)
void attn_kernel(const float* __restrict__ qkv, float* __restrict__ outp) {
    extern __shared__ float smf[];
    float* Qs = smf;                 // 64*128
    float* Ks = Qs + 64*QSTR;        // 64*132
    float* Vs = Ks + 64*KSTR;        // 64*128
    float* Ps = Vs + 64*128;         // 64*64

    const int qt = blockIdx.x, h = blockIdx.y, b = blockIdx.z;
    const int tid = threadIdx.x;
    const int tx = tid & 15, ty = tid >> 4;
    const float scale = 0.08838834764831845f;            // 1/sqrt(128)
    const float slope = exp2f(-0.25f * (float)(h + 1));  // ALiBi, H == next_p2
    const size_t rowbase = (size_t)b * SEQ;

    for (int i = tid; i < 64 * HDIM / 4; i += 256) {
        int r = i >> 5; int c = (i & 31) << 2;
        float4 v = *(const float4*)(qkv + (rowbase + qt*64 + r) * E3 + h*HDIM + c);
        v.x *= scale; v.y *= scale; v.z *= scale; v.w *= scale;
        *(float4*)(Qs + r*QSTR + c) = v;
    }
    float m_i[4], l_i[4];
    float o[4][8];
#pragma unroll
    for (int i = 0; i < 4; i++) {
        m_i[i] = -1e30f; l_i[i] = 0.f;
#pragma unroll
        for (int c = 0; c < 8; c++) o[i][c] = 0.f;
    }
    __syncthreads();

    for (int kt = 0; kt <= qt; kt++) {
        for (int i = tid; i < 64 * HDIM / 4; i += 256) {
            int r = i >> 5; int c = (i & 31) << 2;
            const float* kp = qkv + (rowbase + kt*64 + r) * E3 + D_MODEL + h*HDIM + c;
            *(float4*)(Ks + r*KSTR + c) = *(const float4*)kp;
            *(float4*)(Vs + r*HDIM + c) = *(const float4*)(kp + D_MODEL);
        }
        __syncthreads();

        float sacc[4][4] = {};
#pragma unroll 4
        for (int kb = 0; kb < HDIM; kb += 4) {
            float4 a4[4], b4[4];
#pragma unroll
            for (int i = 0; i < 4; i++)
                a4[i] = *(const float4*)(Qs + (ty*4+i)*QSTR + kb);
#pragma unroll
            for (int j = 0; j < 4; j++)
                b4[j] = *(const float4*)(Ks + (tx + 16*j)*KSTR + kb);
#pragma unroll
            for (int i = 0; i < 4; i++)
#pragma unroll
                for (int j = 0; j < 4; j++) {
                    sacc[i][j] = fmaf(a4[i].x, b4[j].x, sacc[i][j]);
                    sacc[i][j] = fmaf(a4[i].y, b4[j].y, sacc[i][j]);
                    sacc[i][j] = fmaf(a4[i].z, b4[j].z, sacc[i][j]);
                    sacc[i][j] = fmaf(a4[i].w, b4[j].w, sacc[i][j]);
                }
        }

        const int qb = qt*64 + ty*4, kb0 = kt*64;
        float r_[4];
#pragma unroll
        for (int i = 0; i < 4; i++) {
            const int row = ty*4 + i;
            const int qi  = qb + i;
            float v[4];
#pragma unroll
            for (int j = 0; j < 4; j++) {
                int kj = kb0 + tx + 16*j;
                float s = sacc[i][j] + slope * (float)(kj - qi);
                v[j] = (kj > qi) ? -1e30f : s;
            }
            float mx = fmaxf(fmaxf(v[0], v[1]), fmaxf(v[2], v[3]));
            mx = fmaxf(mx, __shfl_xor_sync(0xffffffffu, mx, 1));
            mx = fmaxf(mx, __shfl_xor_sync(0xffffffffu, mx, 2));
            mx = fmaxf(mx, __shfl_xor_sync(0xffffffffu, mx, 4));
            mx = fmaxf(mx, __shfl_xor_sync(0xffffffffu, mx, 8));
            float mn = fmaxf(mx, m_i[i]);
#pragma unroll
            for (int j = 0; j < 4; j++) v[j] = __expf(v[j] - mn);
            float sum = (v[0] + v[1]) + (v[2] + v[3]);
            sum += __shfl_xor_sync(0xffffffffu, sum, 1);
            sum += __shfl_xor_sync(0xffffffffu, sum, 2);
            sum += __shfl_xor_sync(0xffffffffu, sum, 4);
            sum += __shfl_xor_sync(0xffffffffu, sum, 8);
            r_[i] = __expf(m_i[i] - mn);
            m_i[i] = mn;
            l_i[i] = l_i[i] * r_[i] + sum;
            float* prow = Ps + row*PSTR;
#pragma unroll
            for (int j = 0; j < 4; j++) prow[tx + 16*j] = v[j];
        }
        __syncwarp();

#pragma unroll
        for (int i = 0; i < 4; i++)
#pragma unroll
            for (int c = 0; c < 8; c++) o[i][c] *= r_[i];
#pragma unroll 2
        for (int kb2 = 0; kb2 < 64; kb2 += 4) {
            float pv[4][4];
#pragma unroll
            for (int i = 0; i < 4; i++) {
                float4 p = *(const float4*)(Ps + (ty*4+i)*PSTR + kb2);
                pv[i][0] = p.x; pv[i][1] = p.y; pv[i][2] = p.z; pv[i][3] = p.w;
            }
#pragma unroll
            for (int t = 0; t < 4; t++) {
                float4 v0 = *(const float4*)(Vs + (kb2+t)*HDIM + tx*8);
                float4 v1 = *(const float4*)(Vs + (kb2+t)*HDIM + tx*8 + 4);
#pragma unroll
                for (int i = 0; i < 4; i++) {
                    float p = pv[i][t];
                    o[i][0] = fmaf(p, v0.x, o[i][0]);
                    o[i][1] = fmaf(p, v0.y, o[i][1]);
                    o[i][2] = fmaf(p, v0.z, o[i][2]);
                    o[i][3] = fmaf(p, v0.w, o[i][3]);
                    o[i][4] = fmaf(p, v1.x, o[i][4]);
                    o[i][5] = fmaf(p, v1.y, o[i][5]);
                    o[i][6] = fmaf(p, v1.z, o[i][6]);
                    o[i][7] = fmaf(p, v1.w, o[i][7]);
                }
            }
        }
        __syncthreads();
    }

    // Normalize, round to tf32 (what GEMM2's cvt did before), and write
#pragma unroll
    for (int i = 0; i < 4; i++) {
        float inv = 1.f / l_i[i];
        float* op = outp + (rowbase + qt*64 + ty*4 + i) * (size_t)D_MODEL + h*HDIM + tx*8;
        float4 w0, w1;
        w0.x = __uint_as_float(f2tf(o[i][0]*inv));
        w0.y = __uint_as_float(f2tf(o[i][1]*inv));
        w0.z = __uint_as_float(f2tf(o[i][2]*inv));
        w0.w = __uint_as_float(f2tf(o[i][3]*inv));
        w1.x = __uint_as_float(f2tf(o[i][4]*inv));
        w1.y = __uint_as_float(f2tf(o[i][5]*inv));
        w1.z = __uint_as_float(f2tf(o[i][6]*inv));
        w1.w = __uint_as_float(f2tf(o[i][7]*inv));
        *(float4*)op = w0;
        *(float4*)(op + 4) = w1;
    }
}

#define ATTN_SMEM ((64*QSTR + 64*KSTR + 64*128 + 64*PSTR) * (int)sizeof(float))

// ---------------------------------------------------------------------------
extern "C" void kernel_launch(void* const* d_in, const int* in_sizes, int n_in,
                              void* d_out, int out_size) {
    const float* hidden = (const float*)d_in[0];
    const float* w_qkv  = (const float*)d_in[1];
    const float* q_ln_w = (const float*)d_in[2];
    const float* q_ln_b = (const float*)d_in[3];
    const float* k_ln_w = (const float*)d_in[4];
    const float* k_ln_b = (const float*)d_in[5];
    const float* w_out  = (const float*)d_in[6];
    float* out = (float*)d_out;

    float *qkv, *attn;
    uint32_t *hidtf, *wqkvtf, *wouttf;
    cudaGetSymbolAddress((void**)&qkv,    g_qkv);
    cudaGetSymbolAddress((void**)&attn,   g_attn);
    cudaGetSymbolAddress((void**)&hidtf,  g_hid_tf);
    cudaGetSymbolAddress((void**)&wqkvtf, g_wqkv_tf);
    cudaGetSymbolAddress((void**)&wouttf, g_wout_tf);

    cudaFuncSetAttribute(gemm_mma<true>,  cudaFuncAttributeMaxDynamicSharedMemorySize, GEMM_SMEM);
    cudaFuncSetAttribute(gemm_mma<false>, cudaFuncAttributeMaxDynamicSharedMemorySize, GEMM_SMEM);
    cudaFuncSetAttribute(attn_kernel, cudaFuncAttributeMaxDynamicSharedMemorySize, ATTN_SMEM);

    // 0) RNA tf32 pre-conversion (hoisted out of GEMM hot loops)
    cvt_tf32<<<2048, 256>>>((const float4*)hidden, (uint4*)hidtf,  ROWS * D_MODEL / 4);
    cvt_tf32<<<2048, 256>>>((const float4*)w_qkv,  (uint4*)wqkvtf, E3 * D_MODEL / 4);
    cvt_tf32<<<2048, 256>>>((const float4*)w_out,  (uint4*)wouttf, D_MODEL * D_MODEL / 4);

    // 1) QKV projection + clip
    dim3 g1(E3 / 256, ROWS / 128);
    gemm_mma<true><<<g1, 256, GEMM_SMEM>>>(hidtf, wqkvtf, qkv, E3, D_MODEL);

    // 2) fused q/k LayerNorms
    dim3 gl(ROWS, 2);
    ln_kernel<<<gl, 256>>>(qkv, q_ln_w, q_ln_b, k_ln_w, k_ln_b);

    // 3) Flash attention (writes tf32-rounded output)
    dim3 ga(SEQ / 64, NHEADS, BATCH);
    attn_kernel<<<ga, 256, ATTN_SMEM>>>(qkv, attn);

    // 4) Output projection -> d_out
    dim3 g2(D_MODEL / 256, ROWS / 128);
    gemm_mma<false><<<g2, 256, GEMM_SMEM>>>((const uint32_t*)attn, wouttf, out, D_MODEL, D_MODEL);
}

// round 11
// speedup vs baseline: 1.0297x; 1.0297x over previous
#include <cuda_runtime.h>
#include <cstdint>

#define D_MODEL 4096
#define E3      12288
#define NHEADS  32
#define HDIM    128
#define BATCH   2
#define SEQ     2048
#define ROWS    (BATCH*SEQ)   /* 4096 */
#define CLIP_V  8.0f
#define LN_EPS  1e-5f

// Scratch (allocation-free rule: __device__ globals)
__device__ float    g_qkv[(size_t)ROWS * E3];        // post-GEMM1 (q|k|v)
__device__ float    g_attn[(size_t)ROWS * D_MODEL];  // attention out (tf32-rounded)
__device__ uint32_t g_hid_tf[(size_t)ROWS * D_MODEL];     // hidden, tf32 bits
__device__ uint32_t g_wqkv_tf[(size_t)E3 * D_MODEL];      // w_qkv, tf32 bits
__device__ uint32_t g_wout_tf[(size_t)D_MODEL * D_MODEL]; // w_out, tf32 bits

// ===========================================================================
// helpers
// ===========================================================================
__device__ __forceinline__ uint32_t f2tf(float f) {
    uint32_t r;
    asm("cvt.rna.tf32.f32 %0, %1;" : "=r"(r) : "f"(f));
    return r;
}

__device__ __forceinline__ void mma_tf32(float* d, const uint32_t* a, const uint32_t* b) {
    asm volatile(
        "mma.sync.aligned.m16n8k8.row.col.f32.tf32.tf32.f32 "
        "{%0,%1,%2,%3}, {%4,%5,%6,%7}, {%8,%9}, {%0,%1,%2,%3};"
        : "+f"(d[0]), "+f"(d[1]), "+f"(d[2]), "+f"(d[3])
        : "r"(a[0]), "r"(a[1]), "r"(a[2]), "r"(a[3]), "r"(b[0]), "r"(b[1]));
}

__device__ __forceinline__ void cp16(uint32_t saddr, const void* g) {
    asm volatile("cp.async.cg.shared.global [%0], [%1], 16;"
                 :: "r"(saddr), "l"(g) : "memory");
}
#define CP_COMMIT()  asm volatile("cp.async.commit_group;" ::: "memory")
#define CP_WAIT1()   asm volatile("cp.async.wait_group 1;" ::: "memory")

__device__ __forceinline__ void ldsm4(uint32_t& r0, uint32_t& r1, uint32_t& r2,
                                      uint32_t& r3, uint32_t saddr) {
    asm volatile("ldmatrix.sync.aligned.m8n8.x4.shared.b16 {%0,%1,%2,%3}, [%4];"
                 : "=r"(r0), "=r"(r1), "=r"(r2), "=r"(r3) : "r"(saddr));
}

// ===========================================================================
// Elementwise RNA tf32 pre-conversion
// ===========================================================================
__global__ __launch_bounds__(256)
void cvt_tf32(const float4* __restrict__ in, uint4* __restrict__ out, int n4) {
    for (int i = blockIdx.x * 256 + threadIdx.x; i < n4; i += gridDim.x * 256) {
        float4 v = in[i];
        uint4 o;
        o.x = f2tf(v.x); o.y = f2tf(v.y); o.z = f2tf(v.z); o.w = f2tf(v.w);
        out[i] = o;
    }
}

// ===========================================================================
// TF32 GEMM v6: C[m][n] = sum_k A[m][k]*W[n][k]; inputs are tf32 bits.
// CTA tile 128x256, BK=32, 512 threads = 16 warps (2m x 8n), warp tile 64x32.
// 3-stage cp.async + ldmatrix. 25% occupancy for latency hiding.
// grid = (Ntot/256, M/128).
// ===========================================================================
#define LDP2  36
#define A_TW  (128*LDP2)
#define B_TW  (256*LDP2)
#define STG_W (A_TW + B_TW)
#define GEMM_SMEM (STG_W * 3 * 4)   /* 165888 B */

template<bool DO_CLIP>
__global__ __launch_bounds__(512)
void gemm_mma(const uint32_t* __restrict__ A, const uint32_t* __restrict__ W,
              float* __restrict__ C, int Ntot, int K) {
    extern __shared__ uint32_t sm[];

    const int tid  = threadIdx.x;
    const int lane = tid & 31;
    const int warp = tid >> 5;           // 0..15
    const int wm0  = (warp >> 3) << 6;   // 0 or 64
    const int wn0  = (warp & 7) << 5;    // 0,32,...,224
    const int m0 = blockIdx.y << 7, n0 = blockIdx.x << 8;

    const uint32_t* Ab = A + (size_t)m0 * K;
    const uint32_t* Wb = W + (size_t)n0 * K;

    const int arow = tid >> 3;           // 0..63
    const int ac4  = tid & 7;

    const uint32_t sbase = (uint32_t)__cvta_generic_to_shared(sm);
    const uint32_t soffA = ((uint32_t)(arow * LDP2 + ac4 * 4)) * 4;
    const uint32_t sstrA = (uint32_t)(64 * LDP2) * 4;

    // ldmatrix per-lane byte offsets (within a stage)
    const uint32_t l15   = lane & 15;
    const uint32_t csel  = ((lane >> 4) & 1) * 16;   // +4 f32 cols for lanes 16-31
    const uint32_t aOff  = ((wm0 + l15) * LDP2) * 4 + csel;
    const uint32_t bOff  = (uint32_t)(A_TW * 4) + ((wn0 + l15) * LDP2) * 4 + csel;
    const uint32_t mStr  = (uint32_t)(16 * LDP2) * 4;  // 16-row step

    float acc[4][4][4];
#pragma unroll
    for (int a = 0; a < 4; a++)
#pragma unroll
        for (int b = 0; b < 4; b++)
#pragma unroll
            for (int c = 0; c < 4; c++) acc[a][b][c] = 0.f;

    const int NS = K >> 5;

#define ISSUE_STAGE(buf, k0)                                                      \
    do {                                                                          \
        uint32_t _sa = sbase + (uint32_t)(buf) * (STG_W * 4) + soffA;             \
        uint32_t _sb = _sa + (uint32_t)(A_TW * 4);                                \
        _Pragma("unroll")                                                         \
        for (int _i = 0; _i < 2; _i++)                                            \
            cp16(_sa + _i * sstrA,                                                \
                 Ab + (size_t)(arow + 64*_i) * K + (k0) + ac4*4);                 \
        _Pragma("unroll")                                                         \
        for (int _i = 0; _i < 4; _i++)                                            \
            cp16(_sb + _i * sstrA,                                                \
                 Wb + (size_t)(arow + 64*_i) * K + (k0) + ac4*4);                 \
        CP_COMMIT();                                                              \
    } while (0)

    ISSUE_STAGE(0, 0);
    ISSUE_STAGE(1, 32);

    int cur = 0, nxt = 2;
    for (int s = 0; s < NS; s++) {
        CP_WAIT1();
        __syncthreads();
        if (s + 2 < NS) ISSUE_STAGE(nxt, (s + 2) << 5);

        const uint32_t stageB = sbase + (uint32_t)cur * (STG_W * 4);
#pragma unroll
        for (int kk = 0; kk < 4; kk++) {
            const uint32_t kbB = kk * 32;   // 8 words
            uint32_t af[4][4], bf[4][2];
#pragma unroll
            for (int mt = 0; mt < 4; mt++)
                ldsm4(af[mt][0], af[mt][1], af[mt][2], af[mt][3],
                      stageB + aOff + mt * mStr + kbB);
#pragma unroll
            for (int ntp = 0; ntp < 2; ntp++)
                ldsm4(bf[2*ntp][0], bf[2*ntp+1][0], bf[2*ntp][1], bf[2*ntp+1][1],
                      stageB + bOff + ntp * mStr + kbB);
#pragma unroll
            for (int mt = 0; mt < 4; mt++)
#pragma unroll
                for (int nt = 0; nt < 4; nt++)
                    mma_tf32(acc[mt][nt], af[mt], bf[nt]);
        }

        cur = (cur == 2) ? 0 : cur + 1;
        nxt = (nxt == 2) ? 0 : nxt + 1;
    }
#undef ISSUE_STAGE

    // epilogue
#pragma unroll
    for (int mt = 0; mt < 4; mt++) {
#pragma unroll
        for (int nt = 0; nt < 4; nt++) {
            int row = m0 + wm0 + (mt << 4) + (lane >> 2);
            int col = n0 + wn0 + (nt << 3) + ((lane & 3) << 1);
            float2 v0 = make_float2(acc[mt][nt][0], acc[mt][nt][1]);
            float2 v1 = make_float2(acc[mt][nt][2], acc[mt][nt][3]);
            if (DO_CLIP) {
                v0.x = fminf(fmaxf(v0.x, -CLIP_V), CLIP_V);
                v0.y = fminf(fmaxf(v0.y, -CLIP_V), CLIP_V);
                v1.x = fminf(fmaxf(v1.x, -CLIP_V), CLIP_V);
                v1.y = fminf(fmaxf(v1.y, -CLIP_V), CLIP_V);
            }
            *(float2*)(C + (size_t)row * Ntot + col) = v0;
            *(float2*)(C + (size_t)(row + 8) * Ntot + col) = v1;
        }
    }
}

// ---------------------------------------------------------------------------
// Fused q/k LayerNorm (unchanged)
// ---------------------------------------------------------------------------
__global__ __launch_bounds__(256)
void ln_kernel(float* __restrict__ base,
               const float* __restrict__ wq, const float* __restrict__ bq,
               const float* __restrict__ wk, const float* __restrict__ bk) {
    __shared__ float red0[8], red1[8];
    __shared__ float mu_s, inv_s;
    const float* w = blockIdx.y ? wk : wq;
    const float* b = blockIdx.y ? bk : bq;
    float* x = base + (size_t)blockIdx.x * E3 + blockIdx.y * D_MODEL;
    const int tid = threadIdx.x;

    float s = 0.f, s2 = 0.f;
    for (int i = tid; i < D_MODEL; i += 256) {
        float v = x[i]; s += v; s2 += v * v;
    }
#pragma unroll
    for (int o = 16; o; o >>= 1) {
        s  += __shfl_down_sync(0xffffffffu, s,  o);
        s2 += __shfl_down_sync(0xffffffffu, s2, o);
    }
    if ((tid & 31) == 0) { red0[tid >> 5] = s; red1[tid >> 5] = s2; }
    __syncthreads();
    if (tid == 0) {
        float S = 0.f, S2 = 0.f;
#pragma unroll
        for (int i = 0; i < 8; i++) { S += red0[i]; S2 += red1[i]; }
        float mu = S * (1.f / D_MODEL);
        float var = S2 * (1.f / D_MODEL) - mu * mu;
        mu_s = mu;
        inv_s = rsqrtf(var + LN_EPS);
    }
    __syncthreads();
    const float mu = mu_s, inv = inv_s;
    for (int i = tid; i < D_MODEL; i += 256) {
        x[i] = (x[i] - mu) * inv * w[i] + b[i];
    }
}

// ---------------------------------------------------------------------------
// Flash attention v5 (unchanged from R10)
// ---------------------------------------------------------------------------
#define QSTR 128
#define KSTR 132
#define PSTR 64

__global__ __launch_bounds__(256, 2)
void attn_kernel(const float* __restrict__ qkv, float* __restrict__ outp) {
    extern __shared__ float smf[];
    float* Qs = smf;                 // 64*128
    float* Ks = Qs + 64*QSTR;        // 64*132
    float* Vs = Ks + 64*KSTR;        // 64*128
    float* Ps = Vs + 64*128;         // 64*64

    const int qt = blockIdx.x, h = blockIdx.y, b = blockIdx.z;
    const int tid = threadIdx.x;
    const int tx = tid & 15, ty = tid >> 4;
    const float scale = 0.08838834764831845f;            // 1/sqrt(128)
    const float slope = exp2f(-0.25f * (float)(h + 1));  // ALiBi, H == next_p2
    const size_t rowbase = (size_t)b * SEQ;

    for (int i = tid; i < 64 * HDIM / 4; i += 256) {
        int r = i >> 5; int c = (i & 31) << 2;
        float4 v = *(const float4*)(qkv + (rowbase + qt*64 + r) * E3 + h*HDIM + c);
        v.x *= scale; v.y *= scale; v.z *= scale; v.w *= scale;
        *(float4*)(Qs + r*QSTR + c) = v;
    }
    float m_i[4], l_i[4];
    float o[4][8];
#pragma unroll
    for (int i = 0; i < 4; i++) {
        m_i[i] = -1e30f; l_i[i] = 0.f;
#pragma unroll
        for (int c = 0; c < 8; c++) o[i][c] = 0.f;
    }
    __syncthreads();

    for (int kt = 0; kt <= qt; kt++) {
        for (int i = tid; i < 64 * HDIM / 4; i += 256) {
            int r = i >> 5; int c = (i & 31) << 2;
            const float* kp = qkv + (rowbase + kt*64 + r) * E3 + D_MODEL + h*HDIM + c;
            *(float4*)(Ks + r*KSTR + c) = *(const float4*)kp;
            *(float4*)(Vs + r*HDIM + c) = *(const float4*)(kp + D_MODEL);
        }
        __syncthreads();

        float sacc[4][4] = {};
#pragma unroll 4
        for (int kb = 0; kb < HDIM; kb += 4) {
            float4 a4[4], b4[4];
#pragma unroll
            for (int i = 0; i < 4; i++)
                a4[i] = *(const float4*)(Qs + (ty*4+i)*QSTR + kb);
#pragma unroll
            for (int j = 0; j < 4; j++)
                b4[j] = *(const float4*)(Ks + (tx + 16*j)*KSTR + kb);
#pragma unroll
            for (int i = 0; i < 4; i++)
#pragma unroll
                for (int j = 0; j < 4; j++) {
                    sacc[i][j] = fmaf(a4[i].x, b4[j].x, sacc[i][j]);
                    sacc[i][j] = fmaf(a4[i].y, b4[j].y, sacc[i][j]);
                    sacc[i][j] = fmaf(a4[i].z, b4[j].z, sacc[i][j]);
                    sacc[i][j] = fmaf(a4[i].w, b4[j].w, sacc[i][j]);
                }
        }

        const int qb = qt*64 + ty*4, kb0 = kt*64;
        float r_[4];
#pragma unroll
        for (int i = 0; i < 4; i++) {
            const int row = ty*4 + i;
            const int qi  = qb + i;
            float v[4];
#pragma unroll
            for (int j = 0; j < 4; j++) {
                int kj = kb0 + tx + 16*j;
                float s = sacc[i][j] + slope * (float)(kj - qi);
                v[j] = (kj > qi) ? -1e30f : s;
            }
            float mx = fmaxf(fmaxf(v[0], v[1]), fmaxf(v[2], v[3]));
            mx = fmaxf(mx, __shfl_xor_sync(0xffffffffu, mx, 1));
            mx = fmaxf(mx, __shfl_xor_sync(0xffffffffu, mx, 2));
            mx = fmaxf(mx, __shfl_xor_sync(0xffffffffu, mx, 4));
            mx = fmaxf(mx, __shfl_xor_sync(0xffffffffu, mx, 8));
            float mn = fmaxf(mx, m_i[i]);
#pragma unroll
            for (int j = 0; j < 4; j++) v[j] = __expf(v[j] - mn);
            float sum = (v[0] + v[1]) + (v[2] + v[3]);
            sum += __shfl_xor_sync(0xffffffffu, sum, 1);
            sum += __shfl_xor_sync(0xffffffffu, sum, 2);
            sum += __shfl_xor_sync(0xffffffffu, sum, 4);
            sum += __shfl_xor_sync(0xffffffffu, sum, 8);
            r_[i] = __expf(m_i[i] - mn);
            m_i[i] = mn;
            l_i[i] = l_i[i] * r_[i] + sum;
            float* prow = Ps + row*PSTR;
#pragma unroll
            for (int j = 0; j < 4; j++) prow[tx + 16*j] = v[j];
        }
        __syncwarp();

#pragma unroll
        for (int i = 0; i < 4; i++)
#pragma unroll
            for (int c = 0; c < 8; c++) o[i][c] *= r_[i];
#pragma unroll 2
        for (int kb2 = 0; kb2 < 64; kb2 += 4) {
            float pv[4][4];
#pragma unroll
            for (int i = 0; i < 4; i++) {
                float4 p = *(const float4*)(Ps + (ty*4+i)*PSTR + kb2);
                pv[i][0] = p.x; pv[i][1] = p.y; pv[i][2] = p.z; pv[i][3] = p.w;
            }
#pragma unroll
            for (int t = 0; t < 4; t++) {
                float4 v0 = *(const float4*)(Vs + (kb2+t)*HDIM + tx*8);
                float4 v1 = *(const float4*)(Vs + (kb2+t)*HDIM + tx*8 + 4);
#pragma unroll
                for (int i = 0; i < 4; i++) {
                    float p = pv[i][t];
                    o[i][0] = fmaf(p, v0.x, o[i][0]);
                    o[i][1] = fmaf(p, v0.y, o[i][1]);
                    o[i][2] = fmaf(p, v0.z, o[i][2]);
                    o[i][3] = fmaf(p, v0.w, o[i][3]);
                    o[i][4] = fmaf(p, v1.x, o[i][4]);
                    o[i][5] = fmaf(p, v1.y, o[i][5]);
                    o[i][6] = fmaf(p, v1.z, o[i][6]);
                    o[i][7] = fmaf(p, v1.w, o[i][7]);
                }
            }
        }
        __syncthreads();
    }

#pragma unroll
    for (int i = 0; i < 4; i++) {
        float inv = 1.f / l_i[i];
        float* op = outp + (rowbase + qt*64 + ty*4 + i) * (size_t)D_MODEL + h*HDIM + tx*8;
        float4 w0, w1;
        w0.x = __uint_as_float(f2tf(o[i][0]*inv));
        w0.y = __uint_as_float(f2tf(o[i][1]*inv));
        w0.z = __uint_as_float(f2tf(o[i][2]*inv));
        w0.w = __uint_as_float(f2tf(o[i][3]*inv));
        w1.x = __uint_as_float(f2tf(o[i][4]*inv));
        w1.y = __uint_as_float(f2tf(o[i][5]*inv));
        w1.z = __uint_as_float(f2tf(o[i][6]*inv));
        w1.w = __uint_as_float(f2tf(o[i][7]*inv));
        *(float4*)op = w0;
        *(float4*)(op + 4) = w1;
    }
}

#define ATTN_SMEM ((64*QSTR + 64*KSTR + 64*128 + 64*PSTR) * (int)sizeof(float))

// ---------------------------------------------------------------------------
extern "C" void kernel_launch(void* const* d_in, const int* in_sizes, int n_in,
                              void* d_out, int out_size) {
    const float* hidden = (const float*)d_in[0];
    const float* w_qkv  = (const float*)d_in[1];
    const float* q_ln_w = (const float*)d_in[2];
    const float* q_ln_b = (const float*)d_in[3];
    const float* k_ln_w = (const float*)d_in[4];
    const float* k_ln_b = (const float*)d_in[5];
    const float* w_out  = (const float*)d_in[6];
    float* out = (float*)d_out;

    float *qkv, *attn;
    uint32_t *hidtf, *wqkvtf, *wouttf;
    cudaGetSymbolAddress((void**)&qkv,    g_qkv);
    cudaGetSymbolAddress((void**)&attn,   g_attn);
    cudaGetSymbolAddress((void**)&hidtf,  g_hid_tf);
    cudaGetSymbolAddress((void**)&wqkvtf, g_wqkv_tf);
    cudaGetSymbolAddress((void**)&wouttf, g_wout_tf);

    cudaFuncSetAttribute(gemm_mma<true>,  cudaFuncAttributeMaxDynamicSharedMemorySize, GEMM_SMEM);
    cudaFuncSetAttribute(gemm_mma<false>, cudaFuncAttributeMaxDynamicSharedMemorySize, GEMM_SMEM);
    cudaFuncSetAttribute(attn_kernel, cudaFuncAttributeMaxDynamicSharedMemorySize, ATTN_SMEM);

    // 0) RNA tf32 pre-conversion
    cvt_tf32<<<2048, 256>>>((const float4*)hidden, (uint4*)hidtf,  ROWS * D_MODEL / 4);
    cvt_tf32<<<2048, 256>>>((const float4*)w_qkv,  (uint4*)wqkvtf, E3 * D_MODEL / 4);
    cvt_tf32<<<2048, 256>>>((const float4*)w_out,  (uint4*)wouttf, D_MODEL * D_MODEL / 4);

    // 1) QKV projection + clip (512-thread, 16-warp GEMM)
    dim3 g1(E3 / 256, ROWS / 128);
    gemm_mma<true><<<g1, 512, GEMM_SMEM>>>(hidtf, wqkvtf, qkv, E3, D_MODEL);

    // 2) fused q/k LayerNorms
    dim3 gl(ROWS, 2);
    ln_kernel<<<gl, 256>>>(qkv, q_ln_w, q_ln_b, k_ln_w, k_ln_b);

    // 3) Flash attention (writes tf32-rounded output)
    dim3 ga(SEQ / 64, NHEADS, BATCH);
    attn_kernel<<<ga, 256, ATTN_SMEM>>>(qkv, attn);

    // 4) Output projection -> d_out
    dim3 g2(D_MODEL / 256, ROWS / 128);
    gemm_mma<false><<<g2, 512, GEMM_SMEM>>>((const uint32_t*)attn, wouttf, out, D_MODEL, D_MODEL);
}